// round 1
// baseline (speedup 1.0000x reference)
#include <cuda_runtime.h>

#define BB   4
#define CIN  64
#define COUT 64
#define NPTS 8192
#define KNN  16

// Scratch (no allocations allowed): neighbor indices and transposed conv output.
__device__ int   g_idx[BB * NPTS * KNN];          // [b][n][k]       2 MB
__device__ float g_z  [BB * NPTS * COUT];         // zT[b][n][o]     8 MB

// ---------------------------------------------------------------------------
// Kernel 1: brute-force KNN (top-16 smallest squared distances, self included)
// One thread per query point; candidates streamed through shared-memory tiles.
// Distance matches reference expansion: d = (sq_i + sq_j) - 2*<c_i, c_j>.
// ---------------------------------------------------------------------------
__global__ void __launch_bounds__(256) knn_kernel(const float* __restrict__ coords) {
    const int TC = 512;
    __shared__ float4 sh[TC];

    int tid = threadIdx.x;
    int q   = blockIdx.x * 256 + tid;   // global query id over B*N
    int b   = q >> 13;                  // /8192
    int n   = q & (NPTS - 1);

    const float* cb = coords + b * 3 * NPTS;
    float qx = cb[n];
    float qy = cb[NPTS + n];
    float qz = cb[2 * NPTS + n];
    float sqi = (qx * qx + qy * qy) + qz * qz;

    float ds[KNN];
    int   is_[KNN];
#pragma unroll
    for (int s = 0; s < KNN; s++) { ds[s] = __int_as_float(0x7f800000); is_[s] = 0; }

    for (int tb = 0; tb < NPTS; tb += TC) {
        __syncthreads();
#pragma unroll
        for (int u = 0; u < TC / 256; u++) {
            int j = tb + tid + u * 256;
            float cx = cb[j];
            float cy = cb[NPTS + j];
            float cz = cb[2 * NPTS + j];
            float sq = (cx * cx + cy * cy) + cz * cz;
            sh[tid + u * 256] = make_float4(cx, cy, cz, sq);
        }
        __syncthreads();

#pragma unroll 4
        for (int j = 0; j < TC; j++) {
            float4 c = sh[j];
            float inner = fmaf(qz, c.z, fmaf(qy, c.y, qx * c.x));
            float d = fmaf(-2.0f, inner, sqi + c.w);
            if (d < ds[KNN - 1]) {
                // sorted ascending insert (bubble): carries the evicted max out.
                float vd = d;
                int   vi = tb + j;
#pragma unroll
                for (int s = 0; s < KNN; s++) {
                    float od = ds[s];
                    int   oi = is_[s];
                    bool  p  = vd < od;
                    ds[s]  = p ? vd : od;
                    is_[s] = p ? vi : oi;
                    vd     = p ? od : vd;
                    vi     = p ? oi : vi;
                }
            }
        }
    }

    int* op = g_idx + q * KNN;
#pragma unroll
    for (int s = 0; s < KNN; s++) op[s] = is_[s];
}

// ---------------------------------------------------------------------------
// Kernel 2: z[b][n][o] = sum_c W[o][c] * x[b][c][n]   (stored n-major)
// Block: 256 threads = 128 n-columns x 2 o-halves; W staged in smem.
// ---------------------------------------------------------------------------
__global__ void __launch_bounds__(256) gemm_kernel(const float* __restrict__ x,
                                                   const float* __restrict__ W) {
    __shared__ float ws[COUT * CIN];
    int tid = threadIdx.x;
#pragma unroll
    for (int u = 0; u < 4; u++)
        ((float4*)ws)[tid + u * 256] = ((const float4*)W)[tid + u * 256];
    __syncthreads();

    int b     = blockIdx.x >> 6;          // 64 n-tiles of 128 per batch
    int ntile = (blockIdx.x & 63) * 128;
    int nl    = tid & 127;
    int o0    = (tid >> 7) * 32;
    int n     = ntile + nl;

    const float* xb = x + b * CIN * NPTS;

    float acc[32];
#pragma unroll
    for (int i = 0; i < 32; i++) acc[i] = 0.0f;

    for (int c = 0; c < CIN; c += 4) {
        float xv0 = xb[(c + 0) * NPTS + n];
        float xv1 = xb[(c + 1) * NPTS + n];
        float xv2 = xb[(c + 2) * NPTS + n];
        float xv3 = xb[(c + 3) * NPTS + n];
#pragma unroll
        for (int i = 0; i < 32; i++) {
            float4 w4 = *(const float4*)&ws[(o0 + i) * CIN + c];
            acc[i] = fmaf(w4.x, xv0, acc[i]);
            acc[i] = fmaf(w4.y, xv1, acc[i]);
            acc[i] = fmaf(w4.z, xv2, acc[i]);
            acc[i] = fmaf(w4.w, xv3, acc[i]);
        }
    }

    float* zp = g_z + ((size_t)b * NPTS + n) * COUT + o0;
#pragma unroll
    for (int i = 0; i < 32; i += 4)
        *(float4*)&zp[i] = make_float4(acc[i], acc[i + 1], acc[i + 2], acc[i + 3]);
}

// ---------------------------------------------------------------------------
// Kernel 3: y[b][o][n] = max_k z[b][idx[b][n][k]][o]
// Warp per query (lane -> 2 channels); smem transpose for coalesced output.
// ---------------------------------------------------------------------------
__global__ void __launch_bounds__(256) maxgather_kernel(float* __restrict__ y) {
    __shared__ float yt[COUT][33];   // padded: conflict-free column writes

    int tid = threadIdx.x;
    int w   = tid >> 5;
    int l   = tid & 31;
    int b     = blockIdx.x >> 8;          // 256 blocks of 32 queries per batch
    int ntile = (blockIdx.x & 255) * 32;

    const float* zb = g_z + (size_t)b * NPTS * COUT;
    const float NEG_INF = __int_as_float(0xff800000);

    for (int qq = 0; qq < 4; qq++) {
        int nl = w * 4 + qq;
        int n  = ntile + nl;
        const int* ip = g_idx + ((size_t)b * NPTS + n) * KNN;
        float m0 = NEG_INF, m1 = NEG_INF;
#pragma unroll
        for (int k = 0; k < KNN; k++) {
            int r = __ldg(&ip[k]);
            const float* zr = zb + (size_t)r * COUT;
            m0 = fmaxf(m0, zr[l]);
            m1 = fmaxf(m1, zr[l + 32]);
        }
        yt[l][nl]      = m0;
        yt[l + 32][nl] = m1;
    }
    __syncthreads();

#pragma unroll
    for (int e = tid; e < COUT * 32; e += 256) {
        int o  = e >> 5;
        int nl = e & 31;
        y[((size_t)b * COUT + o) * NPTS + ntile + nl] = yt[o][nl];
    }
}

// ---------------------------------------------------------------------------
extern "C" void kernel_launch(void* const* d_in, const int* in_sizes, int n_in,
                              void* d_out, int out_size) {
    const float* x      = (const float*)d_in[0];
    const float* coords = (const float*)d_in[1];
    const float* W      = (const float*)d_in[2];
    float*       out    = (float*)d_out;

    gemm_kernel<<<BB * (NPTS / 128), 256>>>(x, W);
    knn_kernel<<<BB * NPTS / 256, 256>>>(coords);
    maxgather_kernel<<<BB * (NPTS / 32), 256>>>(out);

    // Output tuple is (y, coords): append coords after y.
    cudaMemcpyAsync(out + (size_t)BB * COUT * NPTS, coords,
                    (size_t)BB * 3 * NPTS * sizeof(float),
                    cudaMemcpyDeviceToDevice, 0);
}